// round 2
// baseline (speedup 1.0000x reference)
#include <cuda_runtime.h>
#include <math.h>

#define B_   16
#define T_   256
#define V_   18000
#define NS_  30
#define L_   10
#define G_   3
#define H_   400
#define N_   480      // NS_*B_
#define H3_  1200
#define KDIM 400

// ---------------- scratch (static __device__, allowed) ----------------
__device__ float d_dec[L_*N_*H_];        // decoder inputs, all steps
__device__ float d_gi[L_*N_*H3_];        // input-side GRU gates, all steps
__device__ float d_gh[N_*H3_];           // hidden-side GRU gates (one step)
__device__ float d_h[2][N_*H_];          // ping-pong hidden state
__device__ float d_prob[N_*T_];          // attention scores -> probs
__device__ float d_ctx[N_*H_];           // attention context
__device__ float d_sw[N_];               // pointer-gen switch
__device__ float d_rowsum[N_];           // softmax denominators
__device__ float d_logits[(size_t)N_*V_]; // exp(logits) scratch

// ---------------- K0: build decoder inputs + h0 ----------------
__global__ void k_prep(const float* __restrict__ enc_hidden,
                       const float* __restrict__ emb,
                       const float* __restrict__ slot_emb,
                       const int*   __restrict__ domain_idx,
                       const int*   __restrict__ slotname_idx,
                       const int*   __restrict__ targets)
{
    int n  = blockIdx.x;           // 0..479
    int wi = blockIdx.y;           // 0..9
    int h  = threadIdx.x;          // 0..399
    int slot = n / B_, b = n % B_;
    float v;
    if (wi == 0) {
        v = slot_emb[domain_idx[slot]*H_ + h] + slot_emb[slotname_idx[slot]*H_ + h];
        d_h[0][n*H_ + h] = enc_hidden[b*H_ + h];
    } else {
        int tok = targets[(b*NS_ + slot)*L_ + (wi-1)];
        v = emb[(size_t)tok*H_ + h];
    }
    d_dec[(size_t)(wi*N_ + n)*H_ + h] = v;
}

// ---------------- GEMM: C(MxN) = A(MxK) @ B(NxK)^T, K=400 ----------------
// 128x128 tile, BK=8, 256 threads, 8x8 microtile.
// EPI=0: optional bias-add, plain store. EPI=1: store exp(acc), rowsum atomics.
template<int EPI>
__global__ void k_gemm_abt(const float* __restrict__ A, const float* __restrict__ Bm,
                           float* __restrict__ C, int M, int N,
                           const float* __restrict__ bias)
{
    __shared__ alignas(16) float As[8][128];
    __shared__ alignas(16) float Bs[8][128];
    __shared__ alignas(16) float srow[128];
    const int tid = threadIdx.x;
    const int m0 = blockIdx.y * 128;
    const int n0 = blockIdx.x * 128;
    const int tm = (tid & 15) * 8;
    const int tn = (tid >> 4) * 8;

    float acc[8][8];
    #pragma unroll
    for (int i = 0; i < 8; i++)
        #pragma unroll
        for (int j = 0; j < 8; j++) acc[i][j] = 0.f;

    const int lr = tid >> 1;        // 0..127
    const int lk = (tid & 1) * 4;   // 0 or 4

    for (int k0 = 0; k0 < KDIM; k0 += 8) {
        float4 av = make_float4(0.f,0.f,0.f,0.f);
        float4 bv = make_float4(0.f,0.f,0.f,0.f);
        if (m0 + lr < M) av = *reinterpret_cast<const float4*>(A + (size_t)(m0+lr)*KDIM + k0 + lk);
        if (n0 + lr < N) bv = *reinterpret_cast<const float4*>(Bm + (size_t)(n0+lr)*KDIM + k0 + lk);
        __syncthreads();
        As[lk+0][lr]=av.x; As[lk+1][lr]=av.y; As[lk+2][lr]=av.z; As[lk+3][lr]=av.w;
        Bs[lk+0][lr]=bv.x; Bs[lk+1][lr]=bv.y; Bs[lk+2][lr]=bv.z; Bs[lk+3][lr]=bv.w;
        __syncthreads();
        #pragma unroll
        for (int kk = 0; kk < 8; kk++) {
            float4 a0 = *reinterpret_cast<float4*>(&As[kk][tm]);
            float4 a1 = *reinterpret_cast<float4*>(&As[kk][tm+4]);
            float4 b0 = *reinterpret_cast<float4*>(&Bs[kk][tn]);
            float4 b1 = *reinterpret_cast<float4*>(&Bs[kk][tn+4]);
            float a[8] = {a0.x,a0.y,a0.z,a0.w,a1.x,a1.y,a1.z,a1.w};
            float b[8] = {b0.x,b0.y,b0.z,b0.w,b1.x,b1.y,b1.z,b1.w};
            #pragma unroll
            for (int i = 0; i < 8; i++)
                #pragma unroll
                for (int j = 0; j < 8; j++)
                    acc[i][j] += a[i] * b[j];
        }
    }

    if (EPI == 0) {
        #pragma unroll
        for (int i = 0; i < 8; i++) {
            int m = m0 + tm + i;
            if (m < M) {
                #pragma unroll
                for (int j = 0; j < 8; j++) {
                    int n = n0 + tn + j;
                    if (n < N) {
                        float v = acc[i][j];
                        if (bias) v += bias[n];
                        C[(size_t)m*N + n] = v;
                    }
                }
            }
        }
    } else {
        if (tid < 128) srow[tid] = 0.f;
        __syncthreads();
        #pragma unroll
        for (int i = 0; i < 8; i++) {
            int m = m0 + tm + i;
            float ps = 0.f;
            if (m < M) {
                #pragma unroll
                for (int j = 0; j < 8; j++) {
                    int n = n0 + tn + j;
                    if (n < N) {
                        float e = expf(acc[i][j]);
                        C[(size_t)m*N + n] = e;
                        ps += e;
                    }
                }
                atomicAdd(&srow[tm + i], ps);
            }
        }
        __syncthreads();
        if (tid < 128 && m0 + tid < M)
            atomicAdd(&d_rowsum[m0 + tid], srow[tid]);
    }
}

// ---------------- GRU gate fusion ----------------
__global__ void k_gru(int wi, int pin, int pout)
{
    int n = blockIdx.x;
    int h = threadIdx.x;
    const float* gi = &d_gi[(size_t)(wi*N_ + n)*H3_];
    const float* gh = &d_gh[(size_t)n*H3_];
    float hp = d_h[pin][n*H_ + h];
    float r  = 1.f / (1.f + expf(-(gi[h]        + gh[h])));
    float z  = 1.f / (1.f + expf(-(gi[H_+h]     + gh[H_+h])));
    float nn = tanhf(gi[2*H_+h] + r * gh[2*H_+h]);
    d_h[pout][n*H_ + h] = (1.f - z) * nn + z * hp;
    if (h == 0) d_rowsum[n] = 0.f;   // zero for this step's vocab softmax
}

// ---------------- attention scores: SIMPLE version ----------------
// block per row n (480 blocks), 256 threads (one per t).
// scores[n][t] = dot(h_new[n], enc[b][t]) with mask.
__global__ void k_scores(const float* __restrict__ enc, const int* __restrict__ lens, int pcur)
{
    __shared__ alignas(16) float hsh[H_];
    int n = blockIdx.x;
    int t = threadIdx.x;
    int b = n % B_;
    for (int i = t; i < H_; i += 256) hsh[i] = d_h[pcur][n*H_ + i];
    __syncthreads();
    const float4* e4 = reinterpret_cast<const float4*>(enc + ((size_t)b*T_ + t)*H_);
    const float4* h4 = reinterpret_cast<const float4*>(hsh);
    float s = 0.f;
    #pragma unroll 4
    for (int i = 0; i < H_/4; i++) {
        float4 e = e4[i], hh = h4[i];
        s += e.x*hh.x + e.y*hh.y + e.z*hh.z + e.w*hh.w;
    }
    d_prob[n*T_ + t] = (t < lens[b]) ? s : -1e9f;
}

// ---------------- softmax over T per row ----------------
__global__ void k_softmax_t()
{
    int n = blockIdx.x, t = threadIdx.x;
    __shared__ float red[8];
    int w = t >> 5, ln = t & 31;
    float v = d_prob[n*T_ + t];
    float m = v;
    #pragma unroll
    for (int o = 16; o > 0; o >>= 1) m = fmaxf(m, __shfl_xor_sync(0xffffffffu, m, o));
    if (ln == 0) red[w] = m;
    __syncthreads();
    float mx = red[0];
    #pragma unroll
    for (int i = 1; i < 8; i++) mx = fmaxf(mx, red[i]);
    __syncthreads();
    float e = expf(v - mx);
    float s = e;
    #pragma unroll
    for (int o = 16; o > 0; o >>= 1) s += __shfl_xor_sync(0xffffffffu, s, o);
    if (ln == 0) red[w] = s;
    __syncthreads();
    float sum = 0.f;
    #pragma unroll
    for (int i = 0; i < 8; i++) sum += red[i];
    d_prob[n*T_ + t] = e / sum;
}

// ---------------- context: SIMPLE version ----------------
// block per row n, H_ threads (one per h). ctx[n][h] = sum_t prob[n][t]*enc[b][t][h]
__global__ void k_ctx(const float* __restrict__ enc)
{
    __shared__ float psh[T_];
    int n = blockIdx.x;
    int h = threadIdx.x;
    int b = n % B_;
    if (h < T_) psh[h] = d_prob[n*T_ + h];
    __syncthreads();
    float acc = 0.f;
    #pragma unroll 4
    for (int t = 0; t < T_; t++)
        acc += psh[t] * enc[((size_t)b*T_ + t)*H_ + h];
    d_ctx[n*H_ + h] = acc;
}

// ---------------- switch (+ gates at step 0) ----------------
__device__ __forceinline__ float reduce128(float v, float* sm)
{
    #pragma unroll
    for (int o = 16; o > 0; o >>= 1) v += __shfl_xor_sync(0xffffffffu, v, o);
    int w = threadIdx.x >> 5, ln = threadIdx.x & 31;
    if (ln == 0) sm[w] = v;
    __syncthreads();
    float r = sm[0] + sm[1] + sm[2] + sm[3];
    __syncthreads();
    return r;
}

__global__ void k_switch(int wi, int pcur,
                         const float* __restrict__ w_ratio, const float* __restrict__ b_ratio,
                         const float* __restrict__ w_gate,  const float* __restrict__ b_gate,
                         float* __restrict__ out)
{
    __shared__ float sm[4];
    int n = blockIdx.x, tid = threadIdx.x;
    const float* hn = &d_h[pcur][n*H_];
    const float* cx = &d_ctx[n*H_];
    const float* xx = &d_dec[(size_t)(wi*N_ + n)*H_];
    float p = 0.f;
    for (int j = tid; j < H_; j += 128)
        p += hn[j]*w_ratio[j] + cx[j]*w_ratio[H_+j] + xx[j]*w_ratio[2*H_+j];
    p = reduce128(p, sm);
    if (tid == 0) d_sw[n] = 1.f / (1.f + expf(-(p + b_ratio[0])));
    if (wi == 0) {
        for (int g = 0; g < G_; g++) {
            float q = 0.f;
            for (int j = tid; j < H_; j += 128) q += cx[j] * w_gate[g*H_ + j];
            q = reduce128(q, sm);
            if (tid == 0)
                out[(size_t)N_*L_*V_ + (size_t)n*G_ + g] = q + b_gate[g];
        }
    }
}

// ---------------- finalize vocab part of output ----------------
__global__ void k_finalize(int wi, float* __restrict__ out)
{
    int n = blockIdx.y;
    int v = blockIdx.x * 256 + threadIdx.x;
    if (v >= V_) return;
    float scale = d_sw[n] / d_rowsum[n];
    out[((size_t)n*L_ + wi)*V_ + v] = scale * d_logits[(size_t)n*V_ + v];
}

// ---------------- pointer scatter ----------------
__global__ void k_scatter(int wi, const int* __restrict__ story, float* __restrict__ out)
{
    int n = blockIdx.x, t = threadIdx.x;
    int b0 = n % B_;
    float pv = d_prob[n*T_ + t] * (1.f - d_sw[n]);
    int v = story[b0*T_ + t];
    atomicAdd(&out[((size_t)n*L_ + wi)*V_ + v], pv);
}

// ---------------- host launcher ----------------
extern "C" void kernel_launch(void* const* d_in, const int* in_sizes, int n_in,
                              void* d_out, int out_size)
{
    const float* enc_hidden = (const float*)d_in[0];
    const float* enc_out    = (const float*)d_in[1];
    const float* emb        = (const float*)d_in[2];
    const float* w_ih       = (const float*)d_in[3];
    const float* w_hh       = (const float*)d_in[4];
    const float* b_ih       = (const float*)d_in[5];
    const float* b_hh       = (const float*)d_in[6];
    const float* w_ratio    = (const float*)d_in[7];
    const float* b_ratio    = (const float*)d_in[8];
    const float* w_gate     = (const float*)d_in[9];
    const float* b_gate     = (const float*)d_in[10];
    const float* slot_emb   = (const float*)d_in[11];
    const int*   lens       = (const int*)d_in[12];
    const int*   story      = (const int*)d_in[13];
    const int*   targets    = (const int*)d_in[14];
    const int*   domain_idx = (const int*)d_in[15];
    const int*   slotname_idx = (const int*)d_in[16];
    float* out = (float*)d_out;

    float *p_dec, *p_gi, *p_gh, *p_h, *p_logits;
    cudaGetSymbolAddress((void**)&p_dec, d_dec);
    cudaGetSymbolAddress((void**)&p_gi, d_gi);
    cudaGetSymbolAddress((void**)&p_gh, d_gh);
    cudaGetSymbolAddress((void**)&p_h, d_h);
    cudaGetSymbolAddress((void**)&p_logits, d_logits);

    // Prep: decoder inputs for all steps (teacher forcing known ahead) + h0
    k_prep<<<dim3(N_, L_), H_>>>(enc_hidden, emb, slot_emb, domain_idx, slotname_idx, targets);

    // Input-side GRU gates for ALL steps in one big GEMM: (L*N, 3H)
    k_gemm_abt<0><<<dim3((H3_ + 127)/128, (L_*N_ + 127)/128), 256>>>(
        p_dec, w_ih, p_gi, L_*N_, H3_, b_ih);

    for (int wi = 0; wi < L_; wi++) {
        int pin = wi & 1, pout = (wi + 1) & 1;
        float* hprev = p_h + (size_t)pin  * N_ * H_;
        float* hnew  = p_h + (size_t)pout * N_ * H_;

        // hidden-side gates: (N,3H) = hprev @ W_hh^T + b_hh
        k_gemm_abt<0><<<dim3((H3_ + 127)/128, (N_ + 127)/128), 256>>>(
            hprev, w_hh, p_gh, N_, H3_, b_hh);

        // GRU combine -> h_new ; also zeros rowsum
        k_gru<<<N_, H_>>>(wi, pin, pout);

        // attention scores (masked), softmax over T, context
        k_scores<<<N_, T_>>>(enc_out, lens, pout);
        k_softmax_t<<<N_, T_>>>();
        k_ctx<<<N_, H_>>>(enc_out);

        // pointer-gen switch (+ gates at step 0)
        k_switch<<<N_, 128>>>(wi, pout, w_ratio, b_ratio, w_gate, b_gate, out);

        // vocab logits GEMM with fused exp + rowsum epilogue
        k_gemm_abt<1><<<dim3((V_ + 127)/128, (N_ + 127)/128), 256>>>(
            hnew, emb, p_logits, N_, V_, nullptr);

        // final = switch * p_vocab, then += (1-switch) * pointer probs
        k_finalize<<<dim3((V_ + 255)/256, N_), 256>>>(wi, out);
        k_scatter<<<N_, T_>>>(wi, story, out);
    }
}

// round 6
// speedup vs baseline: 2.5213x; 2.5213x over previous
#include <cuda_runtime.h>
#include <cuda_bf16.h>
#include <math.h>
#include <stdint.h>

#define B_   16
#define T_   256
#define V_   18000
#define NS_  30
#define L_   10
#define G_   3
#define H_   400
#define N_   480      // NS_*B_
#define H3_  1200
#define KDIM 400
#define KP   448      // K padded to 7*64 for bf16 MMA
#define NKC  7        // K chunks of 64

// ---------------- scratch (static __device__, allowed) ----------------
__device__ float d_dec[L_*N_*H_];
__device__ float d_gi[L_*N_*H3_];
__device__ float d_gh[N_*H3_];
__device__ float d_h[2][N_*H_];
__device__ float d_prob[N_*T_];
__device__ float d_ctx[N_*H_];
__device__ float d_sw[N_];
__device__ float d_rowsum[N_];
__device__ float d_logits[(size_t)N_*V_];
__device__ __nv_bfloat16 d_emb_bf[(size_t)V_*KP];   // padded bf16 emb
__device__ __nv_bfloat16 d_h_bf[512*KP];            // padded bf16 h (pad rows/cols stay zero)

// ---------------- emb -> padded bf16 (once per launch) ----------------
__global__ void k_cvt_emb(const float* __restrict__ emb)
{
    size_t i = (size_t)blockIdx.x * 256 + threadIdx.x;
    if (i >= (size_t)V_ * KP) return;
    int c = (int)(i % KP);
    int n = (int)(i / KP);
    float v = (c < H_) ? emb[(size_t)n * H_ + c] : 0.f;
    d_emb_bf[i] = __float2bfloat16(v);
}

// ================= mma.sync helpers (family-portable, sm_80+) =================
__device__ __forceinline__ void ldmat4(uint32_t* r, uint32_t addr)
{
    asm volatile("ldmatrix.sync.aligned.m8n8.x4.shared.b16 {%0,%1,%2,%3}, [%4];"
                 : "=r"(r[0]), "=r"(r[1]), "=r"(r[2]), "=r"(r[3]) : "r"(addr));
}
__device__ __forceinline__ void mma_bf16(float* d, const uint32_t* a, uint32_t b0, uint32_t b1)
{
    asm volatile(
        "mma.sync.aligned.m16n8k16.row.col.f32.bf16.bf16.f32 "
        "{%0,%1,%2,%3}, {%4,%5,%6,%7}, {%8,%9}, {%0,%1,%2,%3};"
        : "+f"(d[0]), "+f"(d[1]), "+f"(d[2]), "+f"(d[3])
        : "r"(a[0]), "r"(a[1]), "r"(a[2]), "r"(a[3]), "r"(b0), "r"(b1));
}

// ---------------- vocab GEMM via mma.sync (fallback HMMA on sm_103) ----------
// C(480x18000) = h_bf(512x448) @ emb_bf(18000x448)^T; epilogue exp + rowsum.
// 256 threads, 128x128 CTA tile, warps 2(m) x 4(n), 64x32 per warp.
__global__ void __launch_bounds__(256) k_vocab_mma(float* __restrict__ logits)
{
    __shared__ alignas(128) uint8_t As[16384];   // 128 rows x 128B (64 bf16) swizzled
    __shared__ alignas(128) uint8_t Bs[16384];
    __shared__ float srow[128];

    const int tid  = threadIdx.x;
    const int lane = tid & 31;
    const int wid  = tid >> 5;
    const int wm   = (wid & 1) * 64;
    const int wn   = (wid >> 1) * 32;
    const int m0   = blockIdx.y * 128;
    const int n0   = blockIdx.x * 128;
    const uint32_t aBase = (uint32_t)__cvta_generic_to_shared(As);
    const uint32_t bBase = (uint32_t)__cvta_generic_to_shared(Bs);

    float acc[4][4][4];
    #pragma unroll
    for (int i = 0; i < 4; i++)
        #pragma unroll
        for (int j = 0; j < 4; j++)
            #pragma unroll
            for (int q = 0; q < 4; q++) acc[i][j][q] = 0.f;

    for (int kc = 0; kc < NKC; kc++) {
        __syncthreads();    // previous chunk's compute done before overwrite
        // A chunk: 128 rows x 64 bf16
        #pragma unroll
        for (int x = tid; x < 1024; x += 256) {
            int r = x >> 3, c = x & 7;
            uint4 v = *(const uint4*)((const char*)d_h_bf + ((size_t)(m0 + r) * KP + kc * 64) * 2 + c * 16);
            uint32_t off = (uint32_t)(r * 128 + c * 16);
            *(uint4*)(As + (off ^ ((off >> 3) & 0x70))) = v;
        }
        // B chunk: 128 emb rows x 64 bf16 (OOB rows -> 0)
        #pragma unroll
        for (int x = tid; x < 1024; x += 256) {
            int r = x >> 3, c = x & 7;
            int gn = n0 + r;
            uint4 v = make_uint4(0u, 0u, 0u, 0u);
            if (gn < V_)
                v = *(const uint4*)((const char*)d_emb_bf + ((size_t)gn * KP + kc * 64) * 2 + c * 16);
            uint32_t off = (uint32_t)(r * 128 + c * 16);
            *(uint4*)(Bs + (off ^ ((off >> 3) & 0x70))) = v;
        }
        __syncthreads();

        #pragma unroll
        for (int ks = 0; ks < 4; ks++) {
            uint32_t af[4][4];
            #pragma unroll
            for (int mt = 0; mt < 4; mt++) {
                int row  = wm + mt * 16 + (lane & 7) + ((lane & 8) ? 8 : 0);
                int koff = ks * 32 + ((lane & 16) ? 16 : 0);
                uint32_t off = (uint32_t)(row * 128 + koff);
                ldmat4(af[mt], aBase + (off ^ ((off >> 3) & 0x70)));
            }
            uint32_t bfr[2][4];
            #pragma unroll
            for (int hh = 0; hh < 2; hh++) {
                int row  = wn + hh * 16 + (lane & 7) + ((lane & 16) ? 8 : 0);
                int koff = ks * 32 + ((lane & 8) ? 16 : 0);
                uint32_t off = (uint32_t)(row * 128 + koff);
                ldmat4(bfr[hh], bBase + (off ^ ((off >> 3) & 0x70)));
            }
            #pragma unroll
            for (int mt = 0; mt < 4; mt++)
                #pragma unroll
                for (int nt = 0; nt < 4; nt++)
                    mma_bf16(acc[mt][nt], af[mt],
                             bfr[nt >> 1][(nt & 1) * 2 + 0],
                             bfr[nt >> 1][(nt & 1) * 2 + 1]);
        }
    }

    // epilogue: exp, store, per-row sums
    if (tid < 128) srow[tid] = 0.f;
    __syncthreads();
    #pragma unroll
    for (int mt = 0; mt < 4; mt++) {
        int rlo = wm + mt * 16 + (lane >> 2);
        int rhi = rlo + 8;
        int gmlo = m0 + rlo, gmhi = m0 + rhi;
        float slo = 0.f, shi = 0.f;
        #pragma unroll
        for (int nt = 0; nt < 4; nt++) {
            int gcol = n0 + wn + nt * 8 + 2 * (lane & 3);
            if (gcol < V_) {
                if (gmlo < N_) {
                    float e0 = __expf(acc[mt][nt][0]);
                    float e1 = __expf(acc[mt][nt][1]);
                    *(float2*)&logits[(size_t)gmlo * V_ + gcol] = make_float2(e0, e1);
                    slo += e0 + e1;
                }
                if (gmhi < N_) {
                    float e2 = __expf(acc[mt][nt][2]);
                    float e3 = __expf(acc[mt][nt][3]);
                    *(float2*)&logits[(size_t)gmhi * V_ + gcol] = make_float2(e2, e3);
                    shi += e2 + e3;
                }
            }
        }
        slo += __shfl_xor_sync(0xffffffffu, slo, 1);
        slo += __shfl_xor_sync(0xffffffffu, slo, 2);
        shi += __shfl_xor_sync(0xffffffffu, shi, 1);
        shi += __shfl_xor_sync(0xffffffffu, shi, 2);
        if ((lane & 3) == 0) {
            if (gmlo < N_) atomicAdd(&srow[rlo], slo);
            if (gmhi < N_) atomicAdd(&srow[rhi], shi);
        }
    }
    __syncthreads();
    if (tid < 128 && m0 + tid < N_) atomicAdd(&d_rowsum[m0 + tid], srow[tid]);
}

// ---------------- K0: build decoder inputs + h0 ----------------
__global__ void k_prep(const float* __restrict__ enc_hidden,
                       const float* __restrict__ emb,
                       const float* __restrict__ slot_emb,
                       const int*   __restrict__ domain_idx,
                       const int*   __restrict__ slotname_idx,
                       const int*   __restrict__ targets)
{
    int n  = blockIdx.x;
    int wi = blockIdx.y;
    int h  = threadIdx.x;
    int slot = n / B_, b = n % B_;
    float v;
    if (wi == 0) {
        v = slot_emb[domain_idx[slot]*H_ + h] + slot_emb[slotname_idx[slot]*H_ + h];
        d_h[0][n*H_ + h] = enc_hidden[b*H_ + h];
    } else {
        int tok = targets[(b*NS_ + slot)*L_ + (wi-1)];
        v = emb[(size_t)tok*H_ + h];
    }
    d_dec[(size_t)(wi*N_ + n)*H_ + h] = v;
}

// ---------------- fp32 SIMT GEMM (GRU gates): C = A @ B^T + bias ----------------
__global__ void k_gemm_abt(const float* __restrict__ A, const float* __restrict__ Bm,
                           float* __restrict__ C, int M, int N,
                           const float* __restrict__ bias)
{
    __shared__ alignas(16) float As[8][128];
    __shared__ alignas(16) float Bs[8][128];
    const int tid = threadIdx.x;
    const int m0 = blockIdx.y * 128;
    const int n0 = blockIdx.x * 128;
    const int tm = (tid & 15) * 8;
    const int tn = (tid >> 4) * 8;

    float acc[8][8];
    #pragma unroll
    for (int i = 0; i < 8; i++)
        #pragma unroll
        for (int j = 0; j < 8; j++) acc[i][j] = 0.f;

    const int lr = tid >> 1;
    const int lk = (tid & 1) * 4;

    for (int k0 = 0; k0 < KDIM; k0 += 8) {
        float4 av = make_float4(0.f,0.f,0.f,0.f);
        float4 bv = make_float4(0.f,0.f,0.f,0.f);
        if (m0 + lr < M) av = *reinterpret_cast<const float4*>(A + (size_t)(m0+lr)*KDIM + k0 + lk);
        if (n0 + lr < N) bv = *reinterpret_cast<const float4*>(Bm + (size_t)(n0+lr)*KDIM + k0 + lk);
        __syncthreads();
        As[lk+0][lr]=av.x; As[lk+1][lr]=av.y; As[lk+2][lr]=av.z; As[lk+3][lr]=av.w;
        Bs[lk+0][lr]=bv.x; Bs[lk+1][lr]=bv.y; Bs[lk+2][lr]=bv.z; Bs[lk+3][lr]=bv.w;
        __syncthreads();
        #pragma unroll
        for (int kk = 0; kk < 8; kk++) {
            float4 a0 = *reinterpret_cast<float4*>(&As[kk][tm]);
            float4 a1 = *reinterpret_cast<float4*>(&As[kk][tm+4]);
            float4 b0 = *reinterpret_cast<float4*>(&Bs[kk][tn]);
            float4 b1 = *reinterpret_cast<float4*>(&Bs[kk][tn+4]);
            float a[8] = {a0.x,a0.y,a0.z,a0.w,a1.x,a1.y,a1.z,a1.w};
            float b[8] = {b0.x,b0.y,b0.z,b0.w,b1.x,b1.y,b1.z,b1.w};
            #pragma unroll
            for (int i = 0; i < 8; i++)
                #pragma unroll
                for (int j = 0; j < 8; j++)
                    acc[i][j] += a[i] * b[j];
        }
    }
    #pragma unroll
    for (int i = 0; i < 8; i++) {
        int m = m0 + tm + i;
        if (m < M) {
            #pragma unroll
            for (int j = 0; j < 8; j++) {
                int n = n0 + tn + j;
                if (n < N) {
                    float v = acc[i][j];
                    if (bias) v += bias[n];
                    C[(size_t)m*N + n] = v;
                }
            }
        }
    }
}

// ---------------- GRU gate fusion (+ bf16 h copy, rowsum zero) ----------------
__global__ void k_gru(int wi, int pin, int pout)
{
    int n = blockIdx.x;
    int h = threadIdx.x;
    const float* gi = &d_gi[(size_t)(wi*N_ + n)*H3_];
    const float* gh = &d_gh[(size_t)n*H3_];
    float hp = d_h[pin][n*H_ + h];
    float r  = 1.f / (1.f + expf(-(gi[h]        + gh[h])));
    float z  = 1.f / (1.f + expf(-(gi[H_+h]     + gh[H_+h])));
    float nn = tanhf(gi[2*H_+h] + r * gh[2*H_+h]);
    float hv = (1.f - z) * nn + z * hp;
    d_h[pout][n*H_ + h] = hv;
    d_h_bf[n*KP + h] = __float2bfloat16(hv);
    if (h == 0) d_rowsum[n] = 0.f;
}

// ---------------- attention scores ----------------
__global__ void k_scores(const float* __restrict__ enc, const int* __restrict__ lens, int pcur)
{
    __shared__ alignas(16) float hsh[H_];
    int n = blockIdx.x;
    int t = threadIdx.x;
    int b = n % B_;
    for (int i = t; i < H_; i += 256) hsh[i] = d_h[pcur][n*H_ + i];
    __syncthreads();
    const float4* e4 = reinterpret_cast<const float4*>(enc + ((size_t)b*T_ + t)*H_);
    const float4* h4 = reinterpret_cast<const float4*>(hsh);
    float s = 0.f;
    #pragma unroll 4
    for (int i = 0; i < H_/4; i++) {
        float4 e = e4[i], hh = h4[i];
        s += e.x*hh.x + e.y*hh.y + e.z*hh.z + e.w*hh.w;
    }
    d_prob[n*T_ + t] = (t < lens[b]) ? s : -1e9f;
}

// ---------------- softmax over T ----------------
__global__ void k_softmax_t()
{
    int n = blockIdx.x, t = threadIdx.x;
    __shared__ float red[8];
    int w = t >> 5, ln = t & 31;
    float v = d_prob[n*T_ + t];
    float m = v;
    #pragma unroll
    for (int o = 16; o > 0; o >>= 1) m = fmaxf(m, __shfl_xor_sync(0xffffffffu, m, o));
    if (ln == 0) red[w] = m;
    __syncthreads();
    float mx = red[0];
    #pragma unroll
    for (int i = 1; i < 8; i++) mx = fmaxf(mx, red[i]);
    __syncthreads();
    float e = expf(v - mx);
    float s = e;
    #pragma unroll
    for (int o = 16; o > 0; o >>= 1) s += __shfl_xor_sync(0xffffffffu, s, o);
    if (ln == 0) red[w] = s;
    __syncthreads();
    float sum = 0.f;
    #pragma unroll
    for (int i = 0; i < 8; i++) sum += red[i];
    d_prob[n*T_ + t] = e / sum;
}

// ---------------- context ----------------
__global__ void k_ctx(const float* __restrict__ enc)
{
    __shared__ float psh[T_];
    int n = blockIdx.x;
    int h = threadIdx.x;
    int b = n % B_;
    if (h < T_) psh[h] = d_prob[n*T_ + h];
    __syncthreads();
    float acc = 0.f;
    #pragma unroll 4
    for (int t = 0; t < T_; t++)
        acc += psh[t] * enc[((size_t)b*T_ + t)*H_ + h];
    d_ctx[n*H_ + h] = acc;
}

// ---------------- switch (+ gates at step 0) ----------------
__device__ __forceinline__ float reduce128(float v, float* sm)
{
    #pragma unroll
    for (int o = 16; o > 0; o >>= 1) v += __shfl_xor_sync(0xffffffffu, v, o);
    int w = threadIdx.x >> 5, ln = threadIdx.x & 31;
    if (ln == 0) sm[w] = v;
    __syncthreads();
    float r = sm[0] + sm[1] + sm[2] + sm[3];
    __syncthreads();
    return r;
}

__global__ void k_switch(int wi, int pcur,
                         const float* __restrict__ w_ratio, const float* __restrict__ b_ratio,
                         const float* __restrict__ w_gate,  const float* __restrict__ b_gate,
                         float* __restrict__ out)
{
    __shared__ float sm[4];
    int n = blockIdx.x, tid = threadIdx.x;
    const float* hn = &d_h[pcur][n*H_];
    const float* cx = &d_ctx[n*H_];
    const float* xx = &d_dec[(size_t)(wi*N_ + n)*H_];
    float p = 0.f;
    for (int j = tid; j < H_; j += 128)
        p += hn[j]*w_ratio[j] + cx[j]*w_ratio[H_+j] + xx[j]*w_ratio[2*H_+j];
    p = reduce128(p, sm);
    if (tid == 0) d_sw[n] = 1.f / (1.f + expf(-(p + b_ratio[0])));
    if (wi == 0) {
        for (int g = 0; g < G_; g++) {
            float q = 0.f;
            for (int j = tid; j < H_; j += 128) q += cx[j] * w_gate[g*H_ + j];
            q = reduce128(q, sm);
            if (tid == 0)
                out[(size_t)N_*L_*V_ + (size_t)n*G_ + g] = q + b_gate[g];
        }
    }
}

// ---------------- finalize vocab part ----------------
__global__ void k_finalize(int wi, float* __restrict__ out)
{
    int n = blockIdx.y;
    int v = blockIdx.x * 256 + threadIdx.x;
    if (v >= V_) return;
    float scale = d_sw[n] / d_rowsum[n];
    out[((size_t)n*L_ + wi)*V_ + v] = scale * d_logits[(size_t)n*V_ + v];
}

// ---------------- pointer scatter ----------------
__global__ void k_scatter(int wi, const int* __restrict__ story, float* __restrict__ out)
{
    int n = blockIdx.x, t = threadIdx.x;
    int b0 = n % B_;
    float pv = d_prob[n*T_ + t] * (1.f - d_sw[n]);
    int v = story[b0*T_ + t];
    atomicAdd(&out[((size_t)n*L_ + wi)*V_ + v], pv);
}

// ---------------- host launcher ----------------
extern "C" void kernel_launch(void* const* d_in, const int* in_sizes, int n_in,
                              void* d_out, int out_size)
{
    const float* enc_hidden = (const float*)d_in[0];
    const float* enc_out    = (const float*)d_in[1];
    const float* emb        = (const float*)d_in[2];
    const float* w_ih       = (const float*)d_in[3];
    const float* w_hh       = (const float*)d_in[4];
    const float* b_ih       = (const float*)d_in[5];
    const float* b_hh       = (const float*)d_in[6];
    const float* w_ratio    = (const float*)d_in[7];
    const float* b_ratio    = (const float*)d_in[8];
    const float* w_gate     = (const float*)d_in[9];
    const float* b_gate     = (const float*)d_in[10];
    const float* slot_emb   = (const float*)d_in[11];
    const int*   lens       = (const int*)d_in[12];
    const int*   story      = (const int*)d_in[13];
    const int*   targets    = (const int*)d_in[14];
    const int*   domain_idx = (const int*)d_in[15];
    const int*   slotname_idx = (const int*)d_in[16];
    float* out = (float*)d_out;

    float *p_dec, *p_gi, *p_gh, *p_h, *p_logits;
    cudaGetSymbolAddress((void**)&p_dec, d_dec);
    cudaGetSymbolAddress((void**)&p_gi, d_gi);
    cudaGetSymbolAddress((void**)&p_gh, d_gh);
    cudaGetSymbolAddress((void**)&p_h, d_h);
    cudaGetSymbolAddress((void**)&p_logits, d_logits);

    // once per launch: padded bf16 embedding
    k_cvt_emb<<<(int)(((size_t)V_*KP + 255)/256), 256>>>(emb);

    // decoder inputs for all steps + h0
    k_prep<<<dim3(N_, L_), H_>>>(enc_hidden, emb, slot_emb, domain_idx, slotname_idx, targets);

    // input-side GRU gates for ALL steps in one GEMM
    k_gemm_abt<<<dim3((H3_ + 127)/128, (L_*N_ + 127)/128), 256>>>(
        p_dec, w_ih, p_gi, L_*N_, H3_, b_ih);

    for (int wi = 0; wi < L_; wi++) {
        int pin = wi & 1, pout = (wi + 1) & 1;
        float* hprev = p_h + (size_t)pin * N_ * H_;

        k_gemm_abt<<<dim3((H3_ + 127)/128, (N_ + 127)/128), 256>>>(
            hprev, w_hh, p_gh, N_, H3_, b_hh);

        k_gru<<<N_, H_>>>(wi, pin, pout);

        k_scores<<<N_, T_>>>(enc_out, lens, pout);
        k_softmax_t<<<N_, T_>>>();
        k_ctx<<<N_, H_>>>(enc_out);

        k_switch<<<N_, 128>>>(wi, pout, w_ratio, b_ratio, w_gate, b_gate, out);

        // vocab GEMM on tensor cores via mma.sync (exp + rowsum fused)
        k_vocab_mma<<<dim3((V_ + 127)/128, 4), 256>>>(p_logits);

        k_finalize<<<dim3((V_ + 255)/256, N_), 256>>>(wi, out);
        k_scatter<<<N_, T_>>>(wi, story, out);
    }
}